// round 13
// baseline (speedup 1.0000x reference)
#include <cuda_runtime.h>
#include <cuda_bf16.h>
#include <cstdint>
#include <math.h>

#define T_TOK   8192
#define H_DIM   1024
#define F_DIM   4096
#define E_NUM   8
#define A_NUM   (2 * T_TOK)

// ---------------- arena: 416MB of words, manually partitioned ----------------
// [XH 4M | XL 4M | W1H 16M | W1L 16M | HH 32M | HL 32M] words
// y (16M words fp32) aliases [0, 16M) -- x/w1 planes are dead by gemm2.
#define MW       (1024 * 1024)
#define XH_OFF   0
#define XL_OFF   (4 * MW)
#define W1H_OFF  (8 * MW)
#define W1L_OFF  (24 * MW)
#define Y_OFF    0
#define HH_OFF   (40 * MW)
#define HL_OFF   (72 * MW)
#define ARENA_W  (104 * MW)

__device__ __align__(256) uint32_t d_arena[ARENA_W];

__device__ int   d_counts[E_NUM];
__device__ int   d_cursor[E_NUM];
__device__ int   d_off[E_NUM];
__device__ int   d_eidx[A_NUM];
__device__ float d_wt[A_NUM];
__device__ int   d_tok[A_NUM];
__device__ int   d_slot[A_NUM];

// ---------------- PTX --------------------------------------------------------
__device__ __forceinline__ void mma16816(float* c, const uint32_t* a, uint32_t b0, uint32_t b1) {
    asm volatile("mma.sync.aligned.m16n8k16.row.col.f32.bf16.bf16.f32 "
                 "{%0,%1,%2,%3}, {%4,%5,%6,%7}, {%8,%9}, {%0,%1,%2,%3};"
                 : "+f"(c[0]), "+f"(c[1]), "+f"(c[2]), "+f"(c[3])
                 : "r"(a[0]), "r"(a[1]), "r"(a[2]), "r"(a[3]), "r"(b0), "r"(b1));
}
__device__ __forceinline__ void split2(float x0, float x1, uint32_t& hi, uint32_t& lo) {
    uint32_t h;
    asm("cvt.rn.bf16x2.f32 %0, %1, %2;" : "=r"(h) : "f"(x1), "f"(x0));
    float f0 = __uint_as_float(h << 16);
    float f1 = __uint_as_float(h & 0xFFFF0000u);
    float r0 = x0 - f0;
    float r1 = x1 - f1;
    uint32_t l;
    asm("cvt.rn.bf16x2.f32 %0, %1, %2;" : "=r"(l) : "f"(r1), "f"(r0));
    hi = h; lo = l;
}

// ---------------- small kernels ----------------------------------------------
__global__ void init_kernel() {
    int i = threadIdx.x;
    if (i < E_NUM) { d_counts[i] = 0; d_cursor[i] = 0; }
}

__global__ void router_kernel(const float* __restrict__ x,
                              const float* __restrict__ rw,
                              const float* __restrict__ rb) {
    int warp = (blockIdx.x * blockDim.x + threadIdx.x) >> 5;
    int lane = threadIdx.x & 31;
    if (warp >= T_TOK) return;
    const float* xr = x + (size_t)warp * H_DIM;
    float acc[E_NUM];
#pragma unroll
    for (int e = 0; e < E_NUM; e++) acc[e] = 0.f;
    for (int k = lane; k < H_DIM; k += 32) {
        float xv = xr[k];
        const float* r = rw + (size_t)k * E_NUM;
#pragma unroll
        for (int e = 0; e < E_NUM; e++) acc[e] += xv * r[e];
    }
#pragma unroll
    for (int off = 16; off; off >>= 1)
#pragma unroll
        for (int e = 0; e < E_NUM; e++)
            acc[e] += __shfl_down_sync(0xffffffffu, acc[e], off);
    if (lane == 0) {
        float l[E_NUM];
#pragma unroll
        for (int e = 0; e < E_NUM; e++) l[e] = acc[e] + rb[e];
        int i0 = 0;
#pragma unroll
        for (int e = 1; e < E_NUM; e++) if (l[e] > l[i0]) i0 = e;
        int i1 = -1;
#pragma unroll
        for (int e = 0; e < E_NUM; e++)
            if (e != i0 && (i1 < 0 || l[e] > l[i1])) i1 = e;
        float m  = l[i0];
        float p1 = __expf(l[i1] - m);
        float s  = 1.f + p1;
        d_eidx[2 * warp + 0] = i0;  d_wt[2 * warp + 0] = 1.f / s;
        d_eidx[2 * warp + 1] = i1;  d_wt[2 * warp + 1] = p1 / s;
        atomicAdd(&d_counts[i0], 1);
        atomicAdd(&d_counts[i1], 1);
    }
}

__global__ void offsets_kernel() {
    if (threadIdx.x == 0) {
        int acc = 0;
        for (int e = 0; e < E_NUM; e++) { d_off[e] = acc; acc += d_counts[e]; }
    }
}

__global__ void scatter_kernel() {
    int t = blockIdx.x * blockDim.x + threadIdx.x;
    if (t >= T_TOK) return;
#pragma unroll
    for (int j = 0; j < 2; j++) {
        int e   = d_eidx[2 * t + j];
        int pos = d_off[e] + atomicAdd(&d_cursor[e], 1);
        d_tok[pos] = t;
        d_slot[2 * t + j] = pos;
    }
}

// ---------------- prepass: split to packed planes ----------------------------
__global__ void convert_x_kernel(const float* __restrict__ x) {
    int idx = blockIdx.x * blockDim.x + threadIdx.x;
    if (idx >= T_TOK * (H_DIM / 2)) return;
    float2 v = ((const float2*)x)[idx];
    split2(v.x, v.y, d_arena[XH_OFF + idx], d_arena[XL_OFF + idx]);
}

__global__ void convert_w1_kernel(const float* __restrict__ W) {
    int idx = blockIdx.x * blockDim.x + threadIdx.x;
    if (idx >= E_NUM * (H_DIM / 2) * F_DIM) return;
    int n    = idx % F_DIM;
    int ekp  = idx / F_DIM;
    size_t s = (size_t)ekp * 2 * F_DIM + n;
    split2(W[s], W[s + F_DIM], d_arena[W1H_OFF + idx], d_arena[W1L_OFF + idx]);
}

// ---------------- grouped GEMM: 256x128 block, 64x64 warp --------------------
#define A_SLAB   520
#define A_L_OFF  (4 * A_SLAB)
#define B_H_OFF  (8 * A_SLAB)
#define B_SLAB   264
#define B_L_OFF  (B_H_OFF + 4 * B_SLAB)
#define SMW_TOT  (B_L_OFF + 4 * B_SLAB)

__device__ __forceinline__ float gelu_tanh(float v) {
    float c = 0.7978845608028654f * (v + 0.044715f * v * v * v);
    return 0.5f * v * (1.f + tanhf(c));
}

template <bool G1>
__global__ __launch_bounds__(256, 1) void moe_gemm(const float* __restrict__ W2,
                                                   const float* __restrict__ bias) {
    constexpr int K_TOT = G1 ? H_DIM : F_DIM;
    constexpr int N_TOT = G1 ? F_DIM : H_DIM;
    constexpr int KW    = K_TOT / 2;
    constexpr int NCH   = K_TOT / 16;

    int e   = blockIdx.z;
    int cnt = d_counts[e];
    int m0  = blockIdx.y * 256;
    if (m0 >= cnt) return;
    int off = d_off[e];
    int n0  = blockIdx.x * 128;

    __shared__ uint32_t smw[SMW_TOT];

    int tid  = threadIdx.x;
    int lane = tid & 31;
    int w    = tid >> 5;
    int wm   = (w >> 1) * 64;
    int wn   = (w & 1) * 64;
    int gid  = lane >> 2;
    int tg   = lane & 3;

    // A plane row (both GEMMs copy-fed from planes)
    int ar = tid;
    int arow_ok = (m0 + ar < cnt);
    size_t arow;
    const uint32_t* Ah;
    const uint32_t* Al;
    if (G1) {
        Ah = d_arena + XH_OFF; Al = d_arena + XL_OFF;
        arow = (size_t)d_tok[off + (arow_ok ? m0 + ar : 0)] * KW;
    } else {
        Ah = d_arena + HH_OFF; Al = d_arena + HL_OFF;
        arow = (size_t)(off + (arow_ok ? m0 + ar : 0)) * KW;
    }
    const uint32_t* Bh = d_arena + W1H_OFF + (size_t)e * KW * N_TOT;  // G1 only
    const uint32_t* Bl = d_arena + W1L_OFF + (size_t)e * KW * N_TOT;
    const float*    B2 = W2 + (size_t)e * (size_t)K_TOT * N_TOT;      // G2 only

    int tg_s = tid >> 6;
    int l64  = tid & 63;

    float acc[4][8][4];
#pragma unroll
    for (int mt = 0; mt < 4; mt++)
#pragma unroll
        for (int nt = 0; nt < 8; nt++)
#pragma unroll
            for (int j = 0; j < 4; j++) acc[mt][nt][j] = 0.f;

    // prefetch chunk 0
    uint4 pah[2], pal[2];
    uint32_t pbh[4], pbl[4];
    float pb[8];
    pah[0] = *(const uint4*)(Ah + arow);     pah[1] = *(const uint4*)(Ah + arow + 4);
    pal[0] = *(const uint4*)(Al + arow);     pal[1] = *(const uint4*)(Al + arow + 4);
    if (G1) {
#pragma unroll
        for (int j = 0; j < 2; j++) {
            pbh[j * 2 + 0] = Bh[(size_t)tg_s * N_TOT + n0 + l64 + 64 * j];
            pbh[j * 2 + 1] = Bh[(size_t)(tg_s + 4) * N_TOT + n0 + l64 + 64 * j];
            pbl[j * 2 + 0] = Bl[(size_t)tg_s * N_TOT + n0 + l64 + 64 * j];
            pbl[j * 2 + 1] = Bl[(size_t)(tg_s + 4) * N_TOT + n0 + l64 + 64 * j];
        }
    } else {
        int rr[4] = {2 * tg_s, 2 * tg_s + 1, 2 * tg_s + 8, 2 * tg_s + 9};
#pragma unroll
        for (int ri = 0; ri < 4; ri++)
#pragma unroll
            for (int j = 0; j < 2; j++)
                pb[ri * 2 + j] = B2[(size_t)rr[ri] * N_TOT + n0 + l64 + 64 * j];
    }

    for (int ch = 0; ch < NCH; ch++) {
        // ---- stage ----
        {
            uint32_t uh[8] = {pah[0].x, pah[0].y, pah[0].z, pah[0].w,
                              pah[1].x, pah[1].y, pah[1].z, pah[1].w};
            uint32_t ul[8] = {pal[0].x, pal[0].y, pal[0].z, pal[0].w,
                              pal[1].x, pal[1].y, pal[1].z, pal[1].w};
#pragma unroll
            for (int kq = 0; kq < 4; kq++) {
                *(uint2*)&smw[kq * A_SLAB + 2 * ar]           = make_uint2(uh[kq], uh[kq + 4]);
                *(uint2*)&smw[A_L_OFF + kq * A_SLAB + 2 * ar] = make_uint2(ul[kq], ul[kq + 4]);
            }
            if (G1) {
#pragma unroll
                for (int j = 0; j < 2; j++) {
                    int n = l64 + 64 * j;
                    *(uint2*)&smw[B_H_OFF + tg_s * B_SLAB + 2 * n] = make_uint2(pbh[j * 2 + 0], pbh[j * 2 + 1]);
                    *(uint2*)&smw[B_L_OFF + tg_s * B_SLAB + 2 * n] = make_uint2(pbl[j * 2 + 0], pbl[j * 2 + 1]);
                }
            } else {
#pragma unroll
                for (int j = 0; j < 2; j++) {
                    uint32_t h0, l0, h1, l1;
                    split2(pb[0 + j], pb[2 + j], h0, l0);
                    split2(pb[4 + j], pb[6 + j], h1, l1);
                    int n = l64 + 64 * j;
                    *(uint2*)&smw[B_H_OFF + tg_s * B_SLAB + 2 * n] = make_uint2(h0, h1);
                    *(uint2*)&smw[B_L_OFF + tg_s * B_SLAB + 2 * n] = make_uint2(l0, l1);
                }
            }
        }
        __syncthreads();

        // ---- prefetch next chunk ----
        if (ch + 1 < NCH) {
            int kb = (ch + 1) * 8;
            pah[0] = *(const uint4*)(Ah + arow + kb);     pah[1] = *(const uint4*)(Ah + arow + kb + 4);
            pal[0] = *(const uint4*)(Al + arow + kb);     pal[1] = *(const uint4*)(Al + arow + kb + 4);
            if (G1) {
#pragma unroll
                for (int j = 0; j < 2; j++) {
                    pbh[j * 2 + 0] = Bh[(size_t)(kb + tg_s) * N_TOT + n0 + l64 + 64 * j];
                    pbh[j * 2 + 1] = Bh[(size_t)(kb + tg_s + 4) * N_TOT + n0 + l64 + 64 * j];
                    pbl[j * 2 + 0] = Bl[(size_t)(kb + tg_s) * N_TOT + n0 + l64 + 64 * j];
                    pbl[j * 2 + 1] = Bl[(size_t)(kb + tg_s + 4) * N_TOT + n0 + l64 + 64 * j];
                }
            } else {
                int k1 = (ch + 1) * 16;
                int rr[4] = {k1 + 2 * tg_s, k1 + 2 * tg_s + 1, k1 + 2 * tg_s + 8, k1 + 2 * tg_s + 9};
#pragma unroll
                for (int ri = 0; ri < 4; ri++)
#pragma unroll
                    for (int j = 0; j < 2; j++)
                        pb[ri * 2 + j] = B2[(size_t)rr[ri] * N_TOT + n0 + l64 + 64 * j];
            }
        }

        // ---- compute ----
        uint32_t bh[8][2], bl[8][2];
#pragma unroll
        for (int nt = 0; nt < 8; nt++) {
            int cb = wn + nt * 8 + gid;
            uint2 H = *(uint2*)&smw[B_H_OFF + tg * B_SLAB + 2 * cb];
            uint2 L = *(uint2*)&smw[B_L_OFF + tg * B_SLAB + 2 * cb];
            bh[nt][0] = H.x; bh[nt][1] = H.y;
            bl[nt][0] = L.x; bl[nt][1] = L.y;
        }
#pragma unroll
        for (int mt = 0; mt < 4; mt++) {
            int ca = wm + mt * 16 + gid;
            uint2 H0 = *(uint2*)&smw[tg * A_SLAB + 2 * ca];
            uint2 H1 = *(uint2*)&smw[tg * A_SLAB + 2 * (ca + 8)];
            uint2 L0 = *(uint2*)&smw[A_L_OFF + tg * A_SLAB + 2 * ca];
            uint2 L1 = *(uint2*)&smw[A_L_OFF + tg * A_SLAB + 2 * (ca + 8)];
            uint32_t ah[4] = {H0.x, H1.x, H0.y, H1.y};
            uint32_t al[4] = {L0.x, L1.x, L0.y, L1.y};
#pragma unroll
            for (int nt = 0; nt < 8; nt++) {
                mma16816(acc[mt][nt], ah, bh[nt][0], bh[nt][1]);
                mma16816(acc[mt][nt], ah, bl[nt][0], bl[nt][1]);
                mma16816(acc[mt][nt], al, bh[nt][0], bh[nt][1]);
            }
        }
        __syncthreads();
    }

    // ---- epilogue ----
    const float* bp = bias + (size_t)e * N_TOT + n0;
    float* ybuf = (float*)(d_arena + Y_OFF);
#pragma unroll
    for (int mt = 0; mt < 4; mt++) {
#pragma unroll
        for (int half = 0; half < 2; half++) {
            int m = m0 + wm + mt * 16 + gid + half * 8;
            if (m >= cnt) continue;
            int slot = off + m;
#pragma unroll
            for (int nt = 0; nt < 8; nt++) {
                int col = wn + nt * 8 + tg * 2;
                float v0 = acc[mt][nt][half * 2 + 0] + bp[col];
                float v1 = acc[mt][nt][half * 2 + 1] + bp[col + 1];
                if (G1) {
                    float g0 = gelu_tanh(v0), g1 = gelu_tanh(v1);
                    uint32_t hw, lw;
                    split2(g0, g1, hw, lw);
                    size_t wi = (size_t)slot * (F_DIM / 2) + ((n0 + col) >> 1);
                    d_arena[HH_OFF + wi] = hw;
                    d_arena[HL_OFF + wi] = lw;
                } else {
                    float2 v; v.x = v0; v.y = v1;
                    *(float2*)(ybuf + (size_t)slot * H_DIM + n0 + col) = v;
                }
            }
        }
    }
}

__global__ void combine_kernel(float* __restrict__ out) {
    int idx = blockIdx.x * blockDim.x + threadIdx.x;
    if (idx >= T_TOK * (H_DIM / 4)) return;
    int t  = idx >> 8;
    int n4 = idx & 255;
    int   s0 = d_slot[2 * t + 0], s1 = d_slot[2 * t + 1];
    float w0 = d_wt[2 * t + 0],  w1 = d_wt[2 * t + 1];
    const float* ybuf = (const float*)(d_arena + Y_OFF);
    float4 a = *(const float4*)(ybuf + (size_t)s0 * H_DIM + n4 * 4);
    float4 b = *(const float4*)(ybuf + (size_t)s1 * H_DIM + n4 * 4);
    float4 o;
    o.x = w0 * a.x + w1 * b.x;
    o.y = w0 * a.y + w1 * b.y;
    o.z = w0 * a.z + w1 * b.z;
    o.w = w0 * a.w + w1 * b.w;
    *(float4*)(out + (size_t)t * H_DIM + n4 * 4) = o;
}

// ---------------- launch -----------------------------------------------------
extern "C" void kernel_launch(void* const* d_in, const int* in_sizes, int n_in,
                              void* d_out, int out_size) {
    const float* x  = (const float*)d_in[0];
    const float* rw = (const float*)d_in[1];
    const float* rb = (const float*)d_in[2];
    const float* w1 = (const float*)d_in[3];
    const float* b1 = (const float*)d_in[4];
    const float* w2 = (const float*)d_in[5];
    const float* b2 = (const float*)d_in[6];
    float* out = (float*)d_out;

    init_kernel<<<1, 32>>>();
    router_kernel<<<T_TOK / 4, 128>>>(x, rw, rb);
    offsets_kernel<<<1, 32>>>();
    scatter_kernel<<<(T_TOK + 255) / 256, 256>>>();

    convert_x_kernel<<<(T_TOK * (H_DIM / 2) + 255) / 256, 256>>>(x);
    convert_w1_kernel<<<(E_NUM * (H_DIM / 2) * F_DIM + 255) / 256, 256>>>(w1);

    dim3 g1(F_DIM / 128, T_TOK / 256, E_NUM);   // (32, 32, 8)
    moe_gemm<true><<<g1, 256>>>(w2, b1);
    dim3 g2(H_DIM / 128, T_TOK / 256, E_NUM);   // (8, 32, 8)
    moe_gemm<false><<<g2, 256>>>(w2, b2);

    combine_kernel<<<(T_TOK * (H_DIM / 4) + 255) / 256, 256>>>(out);
}

// round 14
// speedup vs baseline: 1.3610x; 1.3610x over previous
#include <cuda_runtime.h>
#include <cuda_bf16.h>
#include <cstdint>
#include <math.h>

#define T_TOK   8192
#define H_DIM   1024
#define F_DIM   4096
#define E_NUM   8
#define A_NUM   (2 * T_TOK)

// ---------------- scratch (proven R10 set, 320MB) ----------------------------
__device__ int   d_counts[E_NUM];
__device__ int   d_cursor[E_NUM];
__device__ int   d_off[E_NUM];
__device__ int   d_eidx[A_NUM];
__device__ float d_wt[A_NUM];
__device__ int   d_tok[A_NUM];
__device__ int   d_slot[A_NUM];
__device__ float d_hbuf[(size_t)A_NUM * F_DIM];
__device__ float d_ybuf[(size_t)A_NUM * H_DIM];

// ---------------- PTX --------------------------------------------------------
__device__ __forceinline__ void mma16816(float* c, const uint32_t* a, uint32_t b0, uint32_t b1) {
    asm volatile("mma.sync.aligned.m16n8k16.row.col.f32.bf16.bf16.f32 "
                 "{%0,%1,%2,%3}, {%4,%5,%6,%7}, {%8,%9}, {%0,%1,%2,%3};"
                 : "+f"(c[0]), "+f"(c[1]), "+f"(c[2]), "+f"(c[3])
                 : "r"(a[0]), "r"(a[1]), "r"(a[2]), "r"(a[3]), "r"(b0), "r"(b1));
}
__device__ __forceinline__ void split2(float x0, float x1, uint32_t& hi, uint32_t& lo) {
    uint32_t h;
    asm("cvt.rn.bf16x2.f32 %0, %1, %2;" : "=r"(h) : "f"(x1), "f"(x0));
    float f0 = __uint_as_float(h << 16);
    float f1 = __uint_as_float(h & 0xFFFF0000u);
    float r0 = x0 - f0;
    float r1 = x1 - f1;
    uint32_t l;
    asm("cvt.rn.bf16x2.f32 %0, %1, %2;" : "=r"(l) : "f"(r1), "f"(r0));
    hi = h; lo = l;
}

// ---------------- small kernels (verbatim) -----------------------------------
__global__ void init_kernel() {
    int i = threadIdx.x;
    if (i < E_NUM) { d_counts[i] = 0; d_cursor[i] = 0; }
}

__global__ void router_kernel(const float* __restrict__ x,
                              const float* __restrict__ rw,
                              const float* __restrict__ rb) {
    int warp = (blockIdx.x * blockDim.x + threadIdx.x) >> 5;
    int lane = threadIdx.x & 31;
    if (warp >= T_TOK) return;
    const float* xr = x + (size_t)warp * H_DIM;
    float acc[E_NUM];
#pragma unroll
    for (int e = 0; e < E_NUM; e++) acc[e] = 0.f;
    for (int k = lane; k < H_DIM; k += 32) {
        float xv = xr[k];
        const float* r = rw + (size_t)k * E_NUM;
#pragma unroll
        for (int e = 0; e < E_NUM; e++) acc[e] += xv * r[e];
    }
#pragma unroll
    for (int off = 16; off; off >>= 1)
#pragma unroll
        for (int e = 0; e < E_NUM; e++)
            acc[e] += __shfl_down_sync(0xffffffffu, acc[e], off);
    if (lane == 0) {
        float l[E_NUM];
#pragma unroll
        for (int e = 0; e < E_NUM; e++) l[e] = acc[e] + rb[e];
        int i0 = 0;
#pragma unroll
        for (int e = 1; e < E_NUM; e++) if (l[e] > l[i0]) i0 = e;
        int i1 = -1;
#pragma unroll
        for (int e = 0; e < E_NUM; e++)
            if (e != i0 && (i1 < 0 || l[e] > l[i1])) i1 = e;
        float m  = l[i0];
        float p1 = __expf(l[i1] - m);
        float s  = 1.f + p1;
        d_eidx[2 * warp + 0] = i0;  d_wt[2 * warp + 0] = 1.f / s;
        d_eidx[2 * warp + 1] = i1;  d_wt[2 * warp + 1] = p1 / s;
        atomicAdd(&d_counts[i0], 1);
        atomicAdd(&d_counts[i1], 1);
    }
}

__global__ void offsets_kernel() {
    if (threadIdx.x == 0) {
        int acc = 0;
        for (int e = 0; e < E_NUM; e++) { d_off[e] = acc; acc += d_counts[e]; }
    }
}

__global__ void scatter_kernel() {
    int t = blockIdx.x * blockDim.x + threadIdx.x;
    if (t >= T_TOK) return;
#pragma unroll
    for (int j = 0; j < 2; j++) {
        int e   = d_eidx[2 * t + j];
        int pos = d_off[e] + atomicAdd(&d_cursor[e], 1);
        d_tok[pos] = t;
        d_slot[2 * t + j] = pos;
    }
}

// ---------------- grouped GEMM: 256x128 block, 64x64 warp, double-buffered ---
// Zero-pad slabs + XOR swizzle: word(kp, i) at slab*S + ((2*i + w) ^ (8*slab)),
// slab = kp&3, w = kp>>2.  A: S=512 (256 rows), B: S=256 (128 cols).
// Buffer: [AH 2048 | AL 2048 | BH 1024 | BL 1024] = 6144 words; x2 = 48KB.
#define ABUF_L   2048
#define BBUF_H   4096
#define BBUF_L   5120
#define BUF_W    6144

__device__ __forceinline__ float gelu_tanh(float v) {
    float c = 0.7978845608028654f * (v + 0.044715f * v * v * v);
    return 0.5f * v * (1.f + tanhf(c));
}

template <bool G1>
__global__ __launch_bounds__(256, 1) void moe_gemm(const float* __restrict__ A_in,
                                                   const float* __restrict__ W,
                                                   const float* __restrict__ bias) {
    constexpr int K_TOT = G1 ? H_DIM : F_DIM;
    constexpr int N_TOT = G1 ? F_DIM : H_DIM;
    constexpr int NCH   = K_TOT / 16;

    int e   = blockIdx.z;
    int cnt = d_counts[e];
    int m0  = blockIdx.y * 256;
    if (m0 >= cnt) return;
    int off = d_off[e];
    int n0  = blockIdx.x * 128;
    const float* B = W + (size_t)e * (size_t)K_TOT * N_TOT;

    __shared__ uint32_t smw[2 * BUF_W];   // 49152 bytes

    int tid  = threadIdx.x;
    int lane = tid & 31;
    int w    = tid >> 5;
    int wm   = (w >> 1) * 64;
    int wn   = (w & 1) * 64;
    int gid  = lane >> 2;
    int tg   = lane & 3;

    // A staging: thread = row ar, 16 consecutive k
    int ar = tid;
    int arow_ok = (m0 + ar < cnt);
    const float* arow;
    if (G1) arow = A_in + (size_t)d_tok[off + (arow_ok ? m0 + ar : 0)] * K_TOT;
    else    arow = d_hbuf + (size_t)(off + (arow_ok ? m0 + ar : 0)) * K_TOT;
    // B staging: warp-pair tg_s handles kp rows {2tg_s, 2tg_s+1, +8, +9}
    int tg_s = tid >> 6;
    int l64  = tid & 63;

    float acc[4][8][4];
#pragma unroll
    for (int mt = 0; mt < 4; mt++)
#pragma unroll
        for (int nt = 0; nt < 8; nt++)
#pragma unroll
            for (int j = 0; j < 4; j++) acc[mt][nt][j] = 0.f;

    float4 pa[4];
    float  pb[8];

    auto load_chunk = [&](int ch) {
        int k0 = ch * 16;
#pragma unroll
        for (int j = 0; j < 4; j++) pa[j] = *(const float4*)(arow + k0 + 4 * j);
        int rr[4] = {k0 + 2 * tg_s, k0 + 2 * tg_s + 1, k0 + 2 * tg_s + 8, k0 + 2 * tg_s + 9};
#pragma unroll
        for (int ri = 0; ri < 4; ri++)
#pragma unroll
            for (int j = 0; j < 2; j++)
                pb[ri * 2 + j] = B[(size_t)rr[ri] * N_TOT + n0 + l64 + 64 * j];
    };

    auto stage_chunk = [&](uint32_t* buf) {
        float fa[16] = {pa[0].x, pa[0].y, pa[0].z, pa[0].w,
                        pa[1].x, pa[1].y, pa[1].z, pa[1].w,
                        pa[2].x, pa[2].y, pa[2].z, pa[2].w,
                        pa[3].x, pa[3].y, pa[3].z, pa[3].w};
#pragma unroll
        for (int kq = 0; kq < 4; kq++) {
            uint32_t h0, l0, h1, l1;
            split2(fa[2 * kq],     fa[2 * kq + 1], h0, l0);       // kp = kq
            split2(fa[2 * kq + 8], fa[2 * kq + 9], h1, l1);       // kp = kq+4
            uint32_t a = kq * 512 + ((2 * ar) ^ (8 * kq));
            *(uint2*)&buf[a]          = make_uint2(h0, h1);
            *(uint2*)&buf[ABUF_L + a] = make_uint2(l0, l1);
        }
#pragma unroll
        for (int j = 0; j < 2; j++) {
            uint32_t h0, l0, h1, l1;
            split2(pb[0 + j], pb[2 + j], h0, l0);                 // kp = tg_s
            split2(pb[4 + j], pb[6 + j], h1, l1);                 // kp = tg_s+4
            int n = l64 + 64 * j;
            uint32_t a = tg_s * 256 + ((2 * n) ^ (8 * tg_s));
            *(uint2*)&buf[BBUF_H + a] = make_uint2(h0, h1);
            *(uint2*)&buf[BBUF_L + a] = make_uint2(l0, l1);
        }
    };

    // prologue: chunk0 -> buf0, chunk1 -> regs
    load_chunk(0);
    stage_chunk(smw);
    if (NCH > 1) load_chunk(1);
    __syncthreads();

    for (int ch = 0; ch < NCH; ch++) {
        uint32_t* cur = smw + (ch & 1) * BUF_W;
        // stage chunk ch+1 into other buffer (read last in iter ch-1, synced)
        if (ch + 1 < NCH) stage_chunk(smw + ((ch + 1) & 1) * BUF_W);
        if (ch + 2 < NCH) load_chunk(ch + 2);

        // compute current buffer
        uint32_t bh[8][2], bl[8][2];
#pragma unroll
        for (int nt = 0; nt < 8; nt++) {
            int cb = wn + nt * 8 + gid;
            uint32_t a = tg * 256 + ((2 * cb) ^ (8 * tg));
            uint2 H = *(uint2*)&cur[BBUF_H + a];
            uint2 L = *(uint2*)&cur[BBUF_L + a];
            bh[nt][0] = H.x; bh[nt][1] = H.y;
            bl[nt][0] = L.x; bl[nt][1] = L.y;
        }
#pragma unroll
        for (int mt = 0; mt < 4; mt++) {
            int ca = wm + mt * 16 + gid;
            uint32_t a0 = tg * 512 + ((2 * ca) ^ (8 * tg));
            uint32_t a1 = tg * 512 + ((2 * (ca + 8)) ^ (8 * tg));
            uint2 H0 = *(uint2*)&cur[a0];
            uint2 H1 = *(uint2*)&cur[a1];
            uint2 L0 = *(uint2*)&cur[ABUF_L + a0];
            uint2 L1 = *(uint2*)&cur[ABUF_L + a1];
            uint32_t ah[4] = {H0.x, H1.x, H0.y, H1.y};
            uint32_t al[4] = {L0.x, L1.x, L0.y, L1.y};
#pragma unroll
            for (int nt = 0; nt < 8; nt++) {
                mma16816(acc[mt][nt], ah, bh[nt][0], bh[nt][1]);
                mma16816(acc[mt][nt], ah, bl[nt][0], bl[nt][1]);
                mma16816(acc[mt][nt], al, bh[nt][0], bh[nt][1]);
            }
        }
        __syncthreads();
    }

    // ---- epilogue (R10 verbatim) ----
    const float* bp = bias + (size_t)e * N_TOT + n0;
#pragma unroll
    for (int mt = 0; mt < 4; mt++) {
#pragma unroll
        for (int half = 0; half < 2; half++) {
            int m = m0 + wm + mt * 16 + gid + half * 8;
            if (m >= cnt) continue;
#pragma unroll
            for (int nt = 0; nt < 8; nt++) {
                int col = wn + nt * 8 + tg * 2;
                float v0 = acc[mt][nt][half * 2 + 0] + bp[col];
                float v1 = acc[mt][nt][half * 2 + 1] + bp[col + 1];
                if (G1) {
                    float2 g;
                    g.x = gelu_tanh(v0);
                    g.y = gelu_tanh(v1);
                    *(float2*)(d_hbuf + (size_t)(off + m) * F_DIM + n0 + col) = g;
                } else {
                    float2 v; v.x = v0; v.y = v1;
                    *(float2*)(d_ybuf + (size_t)(off + m) * H_DIM + n0 + col) = v;
                }
            }
        }
    }
}

__global__ void combine_kernel(float* __restrict__ out) {
    int idx = blockIdx.x * blockDim.x + threadIdx.x;
    if (idx >= T_TOK * (H_DIM / 4)) return;
    int t  = idx >> 8;
    int n4 = idx & 255;
    int   s0 = d_slot[2 * t + 0], s1 = d_slot[2 * t + 1];
    float w0 = d_wt[2 * t + 0],  w1 = d_wt[2 * t + 1];
    float4 a = *(const float4*)(d_ybuf + (size_t)s0 * H_DIM + n4 * 4);
    float4 b = *(const float4*)(d_ybuf + (size_t)s1 * H_DIM + n4 * 4);
    float4 o;
    o.x = w0 * a.x + w1 * b.x;
    o.y = w0 * a.y + w1 * b.y;
    o.z = w0 * a.z + w1 * b.z;
    o.w = w0 * a.w + w1 * b.w;
    *(float4*)(out + (size_t)t * H_DIM + n4 * 4) = o;
}

// ---------------- launch -----------------------------------------------------
extern "C" void kernel_launch(void* const* d_in, const int* in_sizes, int n_in,
                              void* d_out, int out_size) {
    const float* x  = (const float*)d_in[0];
    const float* rw = (const float*)d_in[1];
    const float* rb = (const float*)d_in[2];
    const float* w1 = (const float*)d_in[3];
    const float* b1 = (const float*)d_in[4];
    const float* w2 = (const float*)d_in[5];
    const float* b2 = (const float*)d_in[6];
    float* out = (float*)d_out;

    init_kernel<<<1, 32>>>();
    router_kernel<<<T_TOK / 4, 128>>>(x, rw, rb);
    offsets_kernel<<<1, 32>>>();
    scatter_kernel<<<(T_TOK + 255) / 256, 256>>>();

    dim3 g1(F_DIM / 128, T_TOK / 256, E_NUM);   // (32, 32, 8)
    moe_gemm<true><<<g1, 256>>>(x, w1, b1);
    dim3 g2(H_DIM / 128, T_TOK / 256, E_NUM);   // (8, 32, 8)
    moe_gemm<false><<<g2, 256>>>(x, w2, b2);

    combine_kernel<<<(T_TOK * (H_DIM / 4) + 255) / 256, 256>>>(out);
}

// round 15
// speedup vs baseline: 1.5371x; 1.1294x over previous
#include <cuda_runtime.h>
#include <cuda_bf16.h>
#include <cstdint>
#include <math.h>

#define T_TOK   8192
#define H_DIM   1024
#define F_DIM   4096
#define E_NUM   8
#define A_NUM   (2 * T_TOK)

// ---------------- scratch (proven R10 set, 320MB) ----------------------------
__device__ int   d_counts[E_NUM];
__device__ int   d_cursor[E_NUM];
__device__ int   d_off[E_NUM];
__device__ int   d_eidx[A_NUM];
__device__ float d_wt[A_NUM];
__device__ int   d_tok[A_NUM];
__device__ int   d_slot[A_NUM];
__device__ float d_hbuf[(size_t)A_NUM * F_DIM];
__device__ float d_ybuf[(size_t)A_NUM * H_DIM];

// ---------------- PTX --------------------------------------------------------
__device__ __forceinline__ void mma16816(float* c, const uint32_t* a, uint32_t b0, uint32_t b1) {
    asm volatile("mma.sync.aligned.m16n8k16.row.col.f32.bf16.bf16.f32 "
                 "{%0,%1,%2,%3}, {%4,%5,%6,%7}, {%8,%9}, {%0,%1,%2,%3};"
                 : "+f"(c[0]), "+f"(c[1]), "+f"(c[2]), "+f"(c[3])
                 : "r"(a[0]), "r"(a[1]), "r"(a[2]), "r"(a[3]), "r"(b0), "r"(b1));
}
__device__ __forceinline__ void split2(float x0, float x1, uint32_t& hi, uint32_t& lo) {
    uint32_t h;
    asm("cvt.rn.bf16x2.f32 %0, %1, %2;" : "=r"(h) : "f"(x1), "f"(x0));
    float f0 = __uint_as_float(h << 16);
    float f1 = __uint_as_float(h & 0xFFFF0000u);
    float r0 = x0 - f0;
    float r1 = x1 - f1;
    uint32_t l;
    asm("cvt.rn.bf16x2.f32 %0, %1, %2;" : "=r"(l) : "f"(r1), "f"(r0));
    hi = h; lo = l;
}

// ---------------- small kernels (verbatim) -----------------------------------
__global__ void init_kernel() {
    int i = threadIdx.x;
    if (i < E_NUM) { d_counts[i] = 0; d_cursor[i] = 0; }
}

__global__ void router_kernel(const float* __restrict__ x,
                              const float* __restrict__ rw,
                              const float* __restrict__ rb) {
    int warp = (blockIdx.x * blockDim.x + threadIdx.x) >> 5;
    int lane = threadIdx.x & 31;
    if (warp >= T_TOK) return;
    const float* xr = x + (size_t)warp * H_DIM;
    float acc[E_NUM];
#pragma unroll
    for (int e = 0; e < E_NUM; e++) acc[e] = 0.f;
    for (int k = lane; k < H_DIM; k += 32) {
        float xv = xr[k];
        const float* r = rw + (size_t)k * E_NUM;
#pragma unroll
        for (int e = 0; e < E_NUM; e++) acc[e] += xv * r[e];
    }
#pragma unroll
    for (int off = 16; off; off >>= 1)
#pragma unroll
        for (int e = 0; e < E_NUM; e++)
            acc[e] += __shfl_down_sync(0xffffffffu, acc[e], off);
    if (lane == 0) {
        float l[E_NUM];
#pragma unroll
        for (int e = 0; e < E_NUM; e++) l[e] = acc[e] + rb[e];
        int i0 = 0;
#pragma unroll
        for (int e = 1; e < E_NUM; e++) if (l[e] > l[i0]) i0 = e;
        int i1 = -1;
#pragma unroll
        for (int e = 0; e < E_NUM; e++)
            if (e != i0 && (i1 < 0 || l[e] > l[i1])) i1 = e;
        float m  = l[i0];
        float p1 = __expf(l[i1] - m);
        float s  = 1.f + p1;
        d_eidx[2 * warp + 0] = i0;  d_wt[2 * warp + 0] = 1.f / s;
        d_eidx[2 * warp + 1] = i1;  d_wt[2 * warp + 1] = p1 / s;
        atomicAdd(&d_counts[i0], 1);
        atomicAdd(&d_counts[i1], 1);
    }
}

__global__ void offsets_kernel() {
    if (threadIdx.x == 0) {
        int acc = 0;
        for (int e = 0; e < E_NUM; e++) { d_off[e] = acc; acc += d_counts[e]; }
    }
}

__global__ void scatter_kernel() {
    int t = blockIdx.x * blockDim.x + threadIdx.x;
    if (t >= T_TOK) return;
#pragma unroll
    for (int j = 0; j < 2; j++) {
        int e   = d_eidx[2 * t + j];
        int pos = d_off[e] + atomicAdd(&d_cursor[e], 1);
        d_tok[pos] = t;
        d_slot[2 * t + j] = pos;
    }
}

// ---------------- grouped GEMM: 256x128 block, 64x64 warp (R10) --------------
#define A_SLAB   520
#define A_L_OFF  (4 * A_SLAB)
#define B_H_OFF  (8 * A_SLAB)
#define B_SLAB   264
#define B_L_OFF  (B_H_OFF + 4 * B_SLAB)
#define SMW_TOT  (B_L_OFF + 4 * B_SLAB)

__device__ __forceinline__ float gelu_tanh(float v) {
    float c = 0.7978845608028654f * (v + 0.044715f * v * v * v);
    return 0.5f * v * (1.f + tanhf(c));
}

template <bool G1>
__global__ __launch_bounds__(256, 1) void moe_gemm(const float* __restrict__ A_in,
                                                   const float* __restrict__ W,
                                                   const float* __restrict__ bias) {
    constexpr int K_TOT = G1 ? H_DIM : F_DIM;
    constexpr int N_TOT = G1 ? F_DIM : H_DIM;
    constexpr int NCH   = K_TOT / 16;

    int e   = blockIdx.z;
    int cnt = d_counts[e];
    int m0  = blockIdx.y * 256;
    if (m0 >= cnt) return;
    int off = d_off[e];
    int n0  = blockIdx.x * 128;
    const float* B = W + (size_t)e * (size_t)K_TOT * N_TOT;

    __shared__ uint32_t smw[SMW_TOT];

    int tid  = threadIdx.x;
    int lane = tid & 31;
    int w    = tid >> 5;
    int wm   = (w >> 1) * 64;
    int wn   = (w & 1) * 64;
    int gid  = lane >> 2;
    int tg   = lane & 3;

    int ar = tid;
    int arow_ok = (m0 + ar < cnt);
    const float* arow;
    if (G1) arow = A_in + (size_t)d_tok[off + (arow_ok ? m0 + ar : 0)] * K_TOT;
    else    arow = d_hbuf + (size_t)(off + (arow_ok ? m0 + ar : 0)) * K_TOT;
    int tg_s = tid >> 6;
    int l64  = tid & 63;

    float acc[4][8][4];
#pragma unroll
    for (int mt = 0; mt < 4; mt++)
#pragma unroll
        for (int nt = 0; nt < 8; nt++)
#pragma unroll
            for (int j = 0; j < 4; j++) acc[mt][nt][j] = 0.f;

    // prefetch chunk 0
    float4 pa[4];
    float  pb[8];
#pragma unroll
    for (int j = 0; j < 4; j++) pa[j] = *(const float4*)(arow + 4 * j);
    {
        int rr[4] = {2 * tg_s, 2 * tg_s + 1, 2 * tg_s + 8, 2 * tg_s + 9};
#pragma unroll
        for (int ri = 0; ri < 4; ri++)
#pragma unroll
            for (int j = 0; j < 2; j++)
                pb[ri * 2 + j] = B[(size_t)rr[ri] * N_TOT + n0 + l64 + 64 * j];
    }

    for (int ch = 0; ch < NCH; ch++) {
        // ---- stage prefetched chunk ----
        {
            float fa[16] = {pa[0].x, pa[0].y, pa[0].z, pa[0].w,
                            pa[1].x, pa[1].y, pa[1].z, pa[1].w,
                            pa[2].x, pa[2].y, pa[2].z, pa[2].w,
                            pa[3].x, pa[3].y, pa[3].z, pa[3].w};
#pragma unroll
            for (int kq = 0; kq < 4; kq++) {
                uint32_t h0, l0, h1, l1;
                split2(fa[2 * kq],     fa[2 * kq + 1], h0, l0);
                split2(fa[2 * kq + 8], fa[2 * kq + 9], h1, l1);
                *(uint2*)&smw[kq * A_SLAB + 2 * ar]           = make_uint2(h0, h1);
                *(uint2*)&smw[A_L_OFF + kq * A_SLAB + 2 * ar] = make_uint2(l0, l1);
            }
#pragma unroll
            for (int j = 0; j < 2; j++) {
                uint32_t h0, l0, h1, l1;
                split2(pb[0 + j], pb[2 + j], h0, l0);
                split2(pb[4 + j], pb[6 + j], h1, l1);
                int n = l64 + 64 * j;
                *(uint2*)&smw[B_H_OFF + tg_s * B_SLAB + 2 * n] = make_uint2(h0, h1);
                *(uint2*)&smw[B_L_OFF + tg_s * B_SLAB + 2 * n] = make_uint2(l0, l1);
            }
        }
        __syncthreads();

        // ---- prefetch next chunk (overlaps mma) ----
        if (ch + 1 < NCH) {
            int k1 = (ch + 1) * 16;
#pragma unroll
            for (int j = 0; j < 4; j++) pa[j] = *(const float4*)(arow + k1 + 4 * j);
            int rr[4] = {k1 + 2 * tg_s, k1 + 2 * tg_s + 1, k1 + 2 * tg_s + 8, k1 + 2 * tg_s + 9};
#pragma unroll
            for (int ri = 0; ri < 4; ri++)
#pragma unroll
                for (int j = 0; j < 2; j++)
                    pb[ri * 2 + j] = B[(size_t)rr[ri] * N_TOT + n0 + l64 + 64 * j];
        }

        // ---- compute: term-major mma ordering (independent acc chains) ----
        uint32_t bh[8][2], bl[8][2];
#pragma unroll
        for (int nt = 0; nt < 8; nt++) {
            int cb = wn + nt * 8 + gid;
            uint2 H = *(uint2*)&smw[B_H_OFF + tg * B_SLAB + 2 * cb];
            uint2 L = *(uint2*)&smw[B_L_OFF + tg * B_SLAB + 2 * cb];
            bh[nt][0] = H.x; bh[nt][1] = H.y;
            bl[nt][0] = L.x; bl[nt][1] = L.y;
        }
#pragma unroll
        for (int mt = 0; mt < 4; mt++) {
            int ca = wm + mt * 16 + gid;
            uint2 H0 = *(uint2*)&smw[tg * A_SLAB + 2 * ca];
            uint2 H1 = *(uint2*)&smw[tg * A_SLAB + 2 * (ca + 8)];
            uint2 L0 = *(uint2*)&smw[A_L_OFF + tg * A_SLAB + 2 * ca];
            uint2 L1 = *(uint2*)&smw[A_L_OFF + tg * A_SLAB + 2 * (ca + 8)];
            uint32_t ah[4] = {H0.x, H1.x, H0.y, H1.y};
            uint32_t al[4] = {L0.x, L1.x, L0.y, L1.y};
            // per-acc term order unchanged (hh, hl, lh) => bit-identical result;
            // consecutive mmas now hit different accumulators (spacing 8).
#pragma unroll
            for (int nt = 0; nt < 8; nt++)
                mma16816(acc[mt][nt], ah, bh[nt][0], bh[nt][1]);
#pragma unroll
            for (int nt = 0; nt < 8; nt++)
                mma16816(acc[mt][nt], ah, bl[nt][0], bl[nt][1]);
#pragma unroll
            for (int nt = 0; nt < 8; nt++)
                mma16816(acc[mt][nt], al, bh[nt][0], bh[nt][1]);
        }
        __syncthreads();
    }

    // ---- epilogue (R10 verbatim) ----
    const float* bp = bias + (size_t)e * N_TOT + n0;
#pragma unroll
    for (int mt = 0; mt < 4; mt++) {
#pragma unroll
        for (int half = 0; half < 2; half++) {
            int m = m0 + wm + mt * 16 + gid + half * 8;
            if (m >= cnt) continue;
#pragma unroll
            for (int nt = 0; nt < 8; nt++) {
                int col = wn + nt * 8 + tg * 2;
                float v0 = acc[mt][nt][half * 2 + 0] + bp[col];
                float v1 = acc[mt][nt][half * 2 + 1] + bp[col + 1];
                if (G1) {
                    float2 g;
                    g.x = gelu_tanh(v0);
                    g.y = gelu_tanh(v1);
                    *(float2*)(d_hbuf + (size_t)(off + m) * F_DIM + n0 + col) = g;
                } else {
                    float2 v; v.x = v0; v.y = v1;
                    *(float2*)(d_ybuf + (size_t)(off + m) * H_DIM + n0 + col) = v;
                }
            }
        }
    }
}

__global__ void combine_kernel(float* __restrict__ out) {
    int idx = blockIdx.x * blockDim.x + threadIdx.x;
    if (idx >= T_TOK * (H_DIM / 4)) return;
    int t  = idx >> 8;
    int n4 = idx & 255;
    int   s0 = d_slot[2 * t + 0], s1 = d_slot[2 * t + 1];
    float w0 = d_wt[2 * t + 0],  w1 = d_wt[2 * t + 1];
    float4 a = *(const float4*)(d_ybuf + (size_t)s0 * H_DIM + n4 * 4);
    float4 b = *(const float4*)(d_ybuf + (size_t)s1 * H_DIM + n4 * 4);
    float4 o;
    o.x = w0 * a.x + w1 * b.x;
    o.y = w0 * a.y + w1 * b.y;
    o.z = w0 * a.z + w1 * b.z;
    o.w = w0 * a.w + w1 * b.w;
    *(float4*)(out + (size_t)t * H_DIM + n4 * 4) = o;
}

// ---------------- launch -----------------------------------------------------
extern "C" void kernel_launch(void* const* d_in, const int* in_sizes, int n_in,
                              void* d_out, int out_size) {
    const float* x  = (const float*)d_in[0];
    const float* rw = (const float*)d_in[1];
    const float* rb = (const float*)d_in[2];
    const float* w1 = (const float*)d_in[3];
    const float* b1 = (const float*)d_in[4];
    const float* w2 = (const float*)d_in[5];
    const float* b2 = (const float*)d_in[6];
    float* out = (float*)d_out;

    init_kernel<<<1, 32>>>();
    router_kernel<<<T_TOK / 4, 128>>>(x, rw, rb);
    offsets_kernel<<<1, 32>>>();
    scatter_kernel<<<(T_TOK + 255) / 256, 256>>>();

    dim3 g1(F_DIM / 128, T_TOK / 256, E_NUM);   // (32, 32, 8)
    moe_gemm<true><<<g1, 256>>>(x, w1, b1);
    dim3 g2(H_DIM / 128, T_TOK / 256, E_NUM);   // (8, 32, 8)
    moe_gemm<false><<<g2, 256>>>(x, w2, b2);

    combine_kernel<<<(T_TOK * (H_DIM / 4) + 255) / 256, 256>>>(out);
}

// round 16
// speedup vs baseline: 1.7636x; 1.1473x over previous
#include <cuda_runtime.h>
#include <cuda_fp16.h>
#include <cstdint>
#include <math.h>

#define T_TOK   8192
#define H_DIM   1024
#define F_DIM   4096
#define E_NUM   8
#define A_NUM   (2 * T_TOK)

// ---------------- scratch (proven R10 set, 320MB) ----------------------------
__device__ int   d_counts[E_NUM];
__device__ int   d_cursor[E_NUM];
__device__ int   d_off[E_NUM];
__device__ int   d_eidx[A_NUM];
__device__ float d_wt[A_NUM];
__device__ int   d_tok[A_NUM];
__device__ int   d_slot[A_NUM];
__device__ float d_hbuf[(size_t)A_NUM * F_DIM];
__device__ float d_ybuf[(size_t)A_NUM * H_DIM];

// ---------------- PTX --------------------------------------------------------
__device__ __forceinline__ void mma16816h(float* c, const uint32_t* a, uint32_t b0, uint32_t b1) {
    asm volatile("mma.sync.aligned.m16n8k16.row.col.f32.f16.f16.f32 "
                 "{%0,%1,%2,%3}, {%4,%5,%6,%7}, {%8,%9}, {%0,%1,%2,%3};"
                 : "+f"(c[0]), "+f"(c[1]), "+f"(c[2]), "+f"(c[3])
                 : "r"(a[0]), "r"(a[1]), "r"(a[2]), "r"(a[3]), "r"(b0), "r"(b1));
}
// A: exact 2-term fp16 split of two consecutive-k values -> packed f16x2 hi/lo
__device__ __forceinline__ void split2h(float x0, float x1, uint32_t& hi, uint32_t& lo) {
    uint32_t h;
    asm("cvt.rn.f16x2.f32 %0, %1, %2;" : "=r"(h) : "f"(x1), "f"(x0));
    __half2 hh = *reinterpret_cast<__half2*>(&h);
    float f0 = __low2float(hh);
    float f1 = __high2float(hh);
    uint32_t l;
    asm("cvt.rn.f16x2.f32 %0, %1, %2;" : "=r"(l) : "f"(x1 - f1), "f"(x0 - f0));
    hi = h; lo = l;
}
// B: single fp16 (rounding dropped; error ~1.4e-4 RMS)
__device__ __forceinline__ uint32_t pack2h(float x0, float x1) {
    uint32_t h;
    asm("cvt.rn.f16x2.f32 %0, %1, %2;" : "=r"(h) : "f"(x1), "f"(x0));
    return h;
}

// ---------------- small kernels (verbatim) -----------------------------------
__global__ void init_kernel() {
    int i = threadIdx.x;
    if (i < E_NUM) { d_counts[i] = 0; d_cursor[i] = 0; }
}

__global__ void router_kernel(const float* __restrict__ x,
                              const float* __restrict__ rw,
                              const float* __restrict__ rb) {
    int warp = (blockIdx.x * blockDim.x + threadIdx.x) >> 5;
    int lane = threadIdx.x & 31;
    if (warp >= T_TOK) return;
    const float* xr = x + (size_t)warp * H_DIM;
    float acc[E_NUM];
#pragma unroll
    for (int e = 0; e < E_NUM; e++) acc[e] = 0.f;
    for (int k = lane; k < H_DIM; k += 32) {
        float xv = xr[k];
        const float* r = rw + (size_t)k * E_NUM;
#pragma unroll
        for (int e = 0; e < E_NUM; e++) acc[e] += xv * r[e];
    }
#pragma unroll
    for (int off = 16; off; off >>= 1)
#pragma unroll
        for (int e = 0; e < E_NUM; e++)
            acc[e] += __shfl_down_sync(0xffffffffu, acc[e], off);
    if (lane == 0) {
        float l[E_NUM];
#pragma unroll
        for (int e = 0; e < E_NUM; e++) l[e] = acc[e] + rb[e];
        int i0 = 0;
#pragma unroll
        for (int e = 1; e < E_NUM; e++) if (l[e] > l[i0]) i0 = e;
        int i1 = -1;
#pragma unroll
        for (int e = 0; e < E_NUM; e++)
            if (e != i0 && (i1 < 0 || l[e] > l[i1])) i1 = e;
        float m  = l[i0];
        float p1 = __expf(l[i1] - m);
        float s  = 1.f + p1;
        d_eidx[2 * warp + 0] = i0;  d_wt[2 * warp + 0] = 1.f / s;
        d_eidx[2 * warp + 1] = i1;  d_wt[2 * warp + 1] = p1 / s;
        atomicAdd(&d_counts[i0], 1);
        atomicAdd(&d_counts[i1], 1);
    }
}

__global__ void offsets_kernel() {
    if (threadIdx.x == 0) {
        int acc = 0;
        for (int e = 0; e < E_NUM; e++) { d_off[e] = acc; acc += d_counts[e]; }
    }
}

__global__ void scatter_kernel() {
    int t = blockIdx.x * blockDim.x + threadIdx.x;
    if (t >= T_TOK) return;
#pragma unroll
    for (int j = 0; j < 2; j++) {
        int e   = d_eidx[2 * t + j];
        int pos = d_off[e] + atomicAdd(&d_cursor[e], 1);
        d_tok[pos] = t;
        d_slot[2 * t + j] = pos;
    }
}

// ---------------- grouped GEMM: 256x128 block, 64x64 warp, fp16 A-split ------
// smem: AH (4 slabs x 520) | AL (4 x 520) | BH (4 x 264); ~20.9KB
#define A_SLAB   520
#define A_L_OFF  (4 * A_SLAB)
#define B_H_OFF  (8 * A_SLAB)
#define B_SLAB   264
#define SMW_TOT  (B_H_OFF + 4 * B_SLAB)

__device__ __forceinline__ float gelu_tanh(float v) {
    float c = 0.7978845608028654f * (v + 0.044715f * v * v * v);
    return 0.5f * v * (1.f + tanhf(c));
}

template <bool G1>
__global__ __launch_bounds__(256, 1) void moe_gemm(const float* __restrict__ A_in,
                                                   const float* __restrict__ W,
                                                   const float* __restrict__ bias) {
    constexpr int K_TOT = G1 ? H_DIM : F_DIM;
    constexpr int N_TOT = G1 ? F_DIM : H_DIM;
    constexpr int NCH   = K_TOT / 16;

    int e   = blockIdx.z;
    int cnt = d_counts[e];
    int m0  = blockIdx.y * 256;
    if (m0 >= cnt) return;
    int off = d_off[e];
    int n0  = blockIdx.x * 128;
    const float* B = W + (size_t)e * (size_t)K_TOT * N_TOT;

    __shared__ uint32_t smw[SMW_TOT];

    int tid  = threadIdx.x;
    int lane = tid & 31;
    int w    = tid >> 5;
    int wm   = (w >> 1) * 64;
    int wn   = (w & 1) * 64;
    int gid  = lane >> 2;
    int tg   = lane & 3;

    int ar = tid;
    int arow_ok = (m0 + ar < cnt);
    const float* arow;
    if (G1) arow = A_in + (size_t)d_tok[off + (arow_ok ? m0 + ar : 0)] * K_TOT;
    else    arow = d_hbuf + (size_t)(off + (arow_ok ? m0 + ar : 0)) * K_TOT;
    int tg_s = tid >> 6;
    int l64  = tid & 63;

    float acc[4][8][4];
#pragma unroll
    for (int mt = 0; mt < 4; mt++)
#pragma unroll
        for (int nt = 0; nt < 8; nt++)
#pragma unroll
            for (int j = 0; j < 4; j++) acc[mt][nt][j] = 0.f;

    // prefetch chunk 0
    float4 pa[4];
    float  pb[8];
#pragma unroll
    for (int j = 0; j < 4; j++) pa[j] = *(const float4*)(arow + 4 * j);
    {
        int rr[4] = {2 * tg_s, 2 * tg_s + 1, 2 * tg_s + 8, 2 * tg_s + 9};
#pragma unroll
        for (int ri = 0; ri < 4; ri++)
#pragma unroll
            for (int j = 0; j < 2; j++)
                pb[ri * 2 + j] = B[(size_t)rr[ri] * N_TOT + n0 + l64 + 64 * j];
    }

    for (int ch = 0; ch < NCH; ch++) {
        // ---- stage prefetched chunk ----
        {
            float fa[16] = {pa[0].x, pa[0].y, pa[0].z, pa[0].w,
                            pa[1].x, pa[1].y, pa[1].z, pa[1].w,
                            pa[2].x, pa[2].y, pa[2].z, pa[2].w,
                            pa[3].x, pa[3].y, pa[3].z, pa[3].w};
#pragma unroll
            for (int kq = 0; kq < 4; kq++) {
                uint32_t h0, l0, h1, l1;
                split2h(fa[2 * kq],     fa[2 * kq + 1], h0, l0);
                split2h(fa[2 * kq + 8], fa[2 * kq + 9], h1, l1);
                *(uint2*)&smw[kq * A_SLAB + 2 * ar]           = make_uint2(h0, h1);
                *(uint2*)&smw[A_L_OFF + kq * A_SLAB + 2 * ar] = make_uint2(l0, l1);
            }
#pragma unroll
            for (int j = 0; j < 2; j++) {
                uint32_t h0 = pack2h(pb[0 + j], pb[2 + j]);   // kp = tg_s
                uint32_t h1 = pack2h(pb[4 + j], pb[6 + j]);   // kp = tg_s + 4
                int n = l64 + 64 * j;
                *(uint2*)&smw[B_H_OFF + tg_s * B_SLAB + 2 * n] = make_uint2(h0, h1);
            }
        }
        __syncthreads();

        // ---- prefetch next chunk (overlaps mma) ----
        if (ch + 1 < NCH) {
            int k1 = (ch + 1) * 16;
#pragma unroll
            for (int j = 0; j < 4; j++) pa[j] = *(const float4*)(arow + k1 + 4 * j);
            int rr[4] = {k1 + 2 * tg_s, k1 + 2 * tg_s + 1, k1 + 2 * tg_s + 8, k1 + 2 * tg_s + 9};
#pragma unroll
            for (int ri = 0; ri < 4; ri++)
#pragma unroll
                for (int j = 0; j < 2; j++)
                    pb[ri * 2 + j] = B[(size_t)rr[ri] * N_TOT + n0 + l64 + 64 * j];
        }

        // ---- compute: one k16 step, 2 mma per (mt,nt) ----
        uint32_t bh[8][2];
#pragma unroll
        for (int nt = 0; nt < 8; nt++) {
            int cb = wn + nt * 8 + gid;
            uint2 H = *(uint2*)&smw[B_H_OFF + tg * B_SLAB + 2 * cb];
            bh[nt][0] = H.x; bh[nt][1] = H.y;
        }
#pragma unroll
        for (int mt = 0; mt < 4; mt++) {
            int ca = wm + mt * 16 + gid;
            uint2 H0 = *(uint2*)&smw[tg * A_SLAB + 2 * ca];
            uint2 H1 = *(uint2*)&smw[tg * A_SLAB + 2 * (ca + 8)];
            uint2 L0 = *(uint2*)&smw[A_L_OFF + tg * A_SLAB + 2 * ca];
            uint2 L1 = *(uint2*)&smw[A_L_OFF + tg * A_SLAB + 2 * (ca + 8)];
            uint32_t ah[4] = {H0.x, H1.x, H0.y, H1.y};
            uint32_t al[4] = {L0.x, L1.x, L0.y, L1.y};
#pragma unroll
            for (int nt = 0; nt < 8; nt++)
                mma16816h(acc[mt][nt], ah, bh[nt][0], bh[nt][1]);
#pragma unroll
            for (int nt = 0; nt < 8; nt++)
                mma16816h(acc[mt][nt], al, bh[nt][0], bh[nt][1]);
        }
        __syncthreads();
    }

    // ---- epilogue (R10 verbatim) ----
    const float* bp = bias + (size_t)e * N_TOT + n0;
#pragma unroll
    for (int mt = 0; mt < 4; mt++) {
#pragma unroll
        for (int half = 0; half < 2; half++) {
            int m = m0 + wm + mt * 16 + gid + half * 8;
            if (m >= cnt) continue;
#pragma unroll
            for (int nt = 0; nt < 8; nt++) {
                int col = wn + nt * 8 + tg * 2;
                float v0 = acc[mt][nt][half * 2 + 0] + bp[col];
                float v1 = acc[mt][nt][half * 2 + 1] + bp[col + 1];
                if (G1) {
                    float2 g;
                    g.x = gelu_tanh(v0);
                    g.y = gelu_tanh(v1);
                    *(float2*)(d_hbuf + (size_t)(off + m) * F_DIM + n0 + col) = g;
                } else {
                    float2 v; v.x = v0; v.y = v1;
                    *(float2*)(d_ybuf + (size_t)(off + m) * H_DIM + n0 + col) = v;
                }
            }
        }
    }
}

__global__ void combine_kernel(float* __restrict__ out) {
    int idx = blockIdx.x * blockDim.x + threadIdx.x;
    if (idx >= T_TOK * (H_DIM / 4)) return;
    int t  = idx >> 8;
    int n4 = idx & 255;
    int   s0 = d_slot[2 * t + 0], s1 = d_slot[2 * t + 1];
    float w0 = d_wt[2 * t + 0],  w1 = d_wt[2 * t + 1];
    float4 a = *(const float4*)(d_ybuf + (size_t)s0 * H_DIM + n4 * 4);
    float4 b = *(const float4*)(d_ybuf + (size_t)s1 * H_DIM + n4 * 4);
    float4 o;
    o.x = w0 * a.x + w1 * b.x;
    o.y = w0 * a.y + w1 * b.y;
    o.z = w0 * a.z + w1 * b.z;
    o.w = w0 * a.w + w1 * b.w;
    *(float4*)(out + (size_t)t * H_DIM + n4 * 4) = o;
}

// ---------------- launch -----------------------------------------------------
extern "C" void kernel_launch(void* const* d_in, const int* in_sizes, int n_in,
                              void* d_out, int out_size) {
    const float* x  = (const float*)d_in[0];
    const float* rw = (const float*)d_in[1];
    const float* rb = (const float*)d_in[2];
    const float* w1 = (const float*)d_in[3];
    const float* b1 = (const float*)d_in[4];
    const float* w2 = (const float*)d_in[5];
    const float* b2 = (const float*)d_in[6];
    float* out = (float*)d_out;

    init_kernel<<<1, 32>>>();
    router_kernel<<<T_TOK / 4, 128>>>(x, rw, rb);
    offsets_kernel<<<1, 32>>>();
    scatter_kernel<<<(T_TOK + 255) / 256, 256>>>();

    dim3 g1(F_DIM / 128, T_TOK / 256, E_NUM);   // (32, 32, 8)
    moe_gemm<true><<<g1, 256>>>(x, w1, b1);
    dim3 g2(H_DIM / 128, T_TOK / 256, E_NUM);   // (8, 32, 8)
    moe_gemm<false><<<g2, 256>>>(x, w2, b2);

    combine_kernel<<<(T_TOK * (H_DIM / 4) + 255) / 256, 256>>>(out);
}

// round 17
// speedup vs baseline: 2.1592x; 1.2243x over previous
#include <cuda_runtime.h>
#include <cuda_fp16.h>
#include <cstdint>
#include <math.h>

#define T_TOK   8192
#define H_DIM   1024
#define F_DIM   4096
#define E_NUM   8
#define A_NUM   (2 * T_TOK)

// ---------------- scratch (proven set, 320MB) --------------------------------
__device__ int   d_counts[E_NUM];
__device__ int   d_cursor[E_NUM];
__device__ int   d_off[E_NUM];
__device__ int   d_eidx[A_NUM];
__device__ float d_wt[A_NUM];
__device__ int   d_tok[A_NUM];
__device__ int   d_slot[A_NUM];
__device__ float d_hbuf[(size_t)A_NUM * F_DIM];
__device__ float d_ybuf[(size_t)A_NUM * H_DIM];

// ---------------- PTX --------------------------------------------------------
__device__ __forceinline__ void mma16816h(float* c, const uint32_t* a, uint32_t b0, uint32_t b1) {
    asm volatile("mma.sync.aligned.m16n8k16.row.col.f32.f16.f16.f32 "
                 "{%0,%1,%2,%3}, {%4,%5,%6,%7}, {%8,%9}, {%0,%1,%2,%3};"
                 : "+f"(c[0]), "+f"(c[1]), "+f"(c[2]), "+f"(c[3])
                 : "r"(a[0]), "r"(a[1]), "r"(a[2]), "r"(a[3]), "r"(b0), "r"(b1));
}
__device__ __forceinline__ void split2h(float x0, float x1, uint32_t& hi, uint32_t& lo) {
    uint32_t h;
    asm("cvt.rn.f16x2.f32 %0, %1, %2;" : "=r"(h) : "f"(x1), "f"(x0));
    __half2 hh = *reinterpret_cast<__half2*>(&h);
    float f0 = __low2float(hh);
    float f1 = __high2float(hh);
    uint32_t l;
    asm("cvt.rn.f16x2.f32 %0, %1, %2;" : "=r"(l) : "f"(x1 - f1), "f"(x0 - f0));
    hi = h; lo = l;
}
__device__ __forceinline__ uint32_t pack2h(float x0, float x1) {
    uint32_t h;
    asm("cvt.rn.f16x2.f32 %0, %1, %2;" : "=r"(h) : "f"(x1), "f"(x0));
    return h;
}

// ---------------- small kernels (verbatim) -----------------------------------
__global__ void init_kernel() {
    int i = threadIdx.x;
    if (i < E_NUM) { d_counts[i] = 0; d_cursor[i] = 0; }
}

__global__ void router_kernel(const float* __restrict__ x,
                              const float* __restrict__ rw,
                              const float* __restrict__ rb) {
    int warp = (blockIdx.x * blockDim.x + threadIdx.x) >> 5;
    int lane = threadIdx.x & 31;
    if (warp >= T_TOK) return;
    const float* xr = x + (size_t)warp * H_DIM;
    float acc[E_NUM];
#pragma unroll
    for (int e = 0; e < E_NUM; e++) acc[e] = 0.f;
    for (int k = lane; k < H_DIM; k += 32) {
        float xv = xr[k];
        const float* r = rw + (size_t)k * E_NUM;
#pragma unroll
        for (int e = 0; e < E_NUM; e++) acc[e] += xv * r[e];
    }
#pragma unroll
    for (int off = 16; off; off >>= 1)
#pragma unroll
        for (int e = 0; e < E_NUM; e++)
            acc[e] += __shfl_down_sync(0xffffffffu, acc[e], off);
    if (lane == 0) {
        float l[E_NUM];
#pragma unroll
        for (int e = 0; e < E_NUM; e++) l[e] = acc[e] + rb[e];
        int i0 = 0;
#pragma unroll
        for (int e = 1; e < E_NUM; e++) if (l[e] > l[i0]) i0 = e;
        int i1 = -1;
#pragma unroll
        for (int e = 0; e < E_NUM; e++)
            if (e != i0 && (i1 < 0 || l[e] > l[i1])) i1 = e;
        float m  = l[i0];
        float p1 = __expf(l[i1] - m);
        float s  = 1.f + p1;
        d_eidx[2 * warp + 0] = i0;  d_wt[2 * warp + 0] = 1.f / s;
        d_eidx[2 * warp + 1] = i1;  d_wt[2 * warp + 1] = p1 / s;
        atomicAdd(&d_counts[i0], 1);
        atomicAdd(&d_counts[i1], 1);
    }
}

__global__ void offsets_kernel() {
    if (threadIdx.x == 0) {
        int acc = 0;
        for (int e = 0; e < E_NUM; e++) { d_off[e] = acc; acc += d_counts[e]; }
    }
}

__global__ void scatter_kernel() {
    int t = blockIdx.x * blockDim.x + threadIdx.x;
    if (t >= T_TOK) return;
#pragma unroll
    for (int j = 0; j < 2; j++) {
        int e   = d_eidx[2 * t + j];
        int pos = d_off[e] + atomicAdd(&d_cursor[e], 1);
        d_tok[pos] = t;
        d_slot[2 * t + j] = pos;
    }
}

// ---------------- grouped GEMM: 256x128 block, 512 thr, 64x32 warp -----------
// smem: AH (4 slabs x 520) | AL (4 x 520) | BH (4 x 264); ~20.9KB
#define A_SLAB   520
#define A_L_OFF  (4 * A_SLAB)
#define B_H_OFF  (8 * A_SLAB)
#define B_SLAB   264
#define SMW_TOT  (B_H_OFF + 4 * B_SLAB)

__device__ __forceinline__ float gelu_tanh(float v) {
    float c = 0.7978845608028654f * (v + 0.044715f * v * v * v);
    return 0.5f * v * (1.f + tanhf(c));
}

template <bool G1>
__global__ __launch_bounds__(512, 1) void moe_gemm(const float* __restrict__ A_in,
                                                   const float* __restrict__ W,
                                                   const float* __restrict__ bias) {
    constexpr int K_TOT = G1 ? H_DIM : F_DIM;
    constexpr int N_TOT = G1 ? F_DIM : H_DIM;
    constexpr int NCH   = K_TOT / 16;

    int e   = blockIdx.z;
    int cnt = d_counts[e];
    int m0  = blockIdx.y * 256;
    if (m0 >= cnt) return;
    int off = d_off[e];
    int n0  = blockIdx.x * 128;
    const float* B = W + (size_t)e * (size_t)K_TOT * N_TOT;

    __shared__ uint32_t smw[SMW_TOT];

    int tid  = threadIdx.x;
    int lane = tid & 31;
    int w    = tid >> 5;          // 0..15
    int wm   = (w >> 2) * 64;     // 4 m-warps x 64
    int wn   = (w & 3) * 32;      // 4 n-warps x 32
    int gid  = lane >> 2;
    int tg   = lane & 3;

    // A staging: 2 threads per row; half = k-halves {0..7} / {8..15}
    int ar   = tid >> 1;          // 0..255
    int half = tid & 1;
    int arow_ok = (m0 + ar < cnt);
    const float* arow;
    if (G1) arow = A_in + (size_t)d_tok[off + (arow_ok ? m0 + ar : 0)] * K_TOT;
    else    arow = d_hbuf + (size_t)(off + (arow_ok ? m0 + ar : 0)) * K_TOT;
    // B staging: thread -> (kp-group tg_s, col n)
    int tg_s = tid >> 7;          // 0..3
    int bn   = tid & 127;

    float acc[4][4][4];
#pragma unroll
    for (int mt = 0; mt < 4; mt++)
#pragma unroll
        for (int nt = 0; nt < 4; nt++)
#pragma unroll
            for (int j = 0; j < 4; j++) acc[mt][nt][j] = 0.f;

    // prefetch chunk 0
    float4 pa[2];
    float  pb[4];
    pa[0] = *(const float4*)(arow + half * 8);
    pa[1] = *(const float4*)(arow + half * 8 + 4);
    {
        int rr[4] = {2 * tg_s, 2 * tg_s + 1, 2 * tg_s + 8, 2 * tg_s + 9};
#pragma unroll
        for (int ri = 0; ri < 4; ri++)
            pb[ri] = B[(size_t)rr[ri] * N_TOT + n0 + bn];
    }

    for (int ch = 0; ch < NCH; ch++) {
        // ---- stage prefetched chunk ----
        {
            float fa[8] = {pa[0].x, pa[0].y, pa[0].z, pa[0].w,
                           pa[1].x, pa[1].y, pa[1].z, pa[1].w};
            // thread's k-pairs: kp = half*4 + kq2 -> slab kq2, word index half
#pragma unroll
            for (int kq2 = 0; kq2 < 4; kq2++) {
                uint32_t h, l;
                split2h(fa[2 * kq2], fa[2 * kq2 + 1], h, l);
                smw[kq2 * A_SLAB + 2 * ar + half]           = h;
                smw[A_L_OFF + kq2 * A_SLAB + 2 * ar + half] = l;
            }
            uint32_t h0 = pack2h(pb[0], pb[1]);   // kp = tg_s
            uint32_t h1 = pack2h(pb[2], pb[3]);   // kp = tg_s + 4
            *(uint2*)&smw[B_H_OFF + tg_s * B_SLAB + 2 * bn] = make_uint2(h0, h1);
        }
        __syncthreads();

        // ---- prefetch next chunk (overlaps mma) ----
        if (ch + 1 < NCH) {
            int k1 = (ch + 1) * 16;
            pa[0] = *(const float4*)(arow + k1 + half * 8);
            pa[1] = *(const float4*)(arow + k1 + half * 8 + 4);
            int rr[4] = {k1 + 2 * tg_s, k1 + 2 * tg_s + 1, k1 + 2 * tg_s + 8, k1 + 2 * tg_s + 9};
#pragma unroll
            for (int ri = 0; ri < 4; ri++)
                pb[ri] = B[(size_t)rr[ri] * N_TOT + n0 + bn];
        }

        // ---- compute: one k16 step, 2 mma per (mt,nt) ----
        uint32_t bh[4][2];
#pragma unroll
        for (int nt = 0; nt < 4; nt++) {
            int cb = wn + nt * 8 + gid;
            uint2 H = *(uint2*)&smw[B_H_OFF + tg * B_SLAB + 2 * cb];
            bh[nt][0] = H.x; bh[nt][1] = H.y;
        }
#pragma unroll
        for (int mt = 0; mt < 4; mt++) {
            int ca = wm + mt * 16 + gid;
            uint2 H0 = *(uint2*)&smw[tg * A_SLAB + 2 * ca];
            uint2 H1 = *(uint2*)&smw[tg * A_SLAB + 2 * (ca + 8)];
            uint2 L0 = *(uint2*)&smw[A_L_OFF + tg * A_SLAB + 2 * ca];
            uint2 L1 = *(uint2*)&smw[A_L_OFF + tg * A_SLAB + 2 * (ca + 8)];
            uint32_t ah[4] = {H0.x, H1.x, H0.y, H1.y};
            uint32_t al[4] = {L0.x, L1.x, L0.y, L1.y};
#pragma unroll
            for (int nt = 0; nt < 4; nt++)
                mma16816h(acc[mt][nt], ah, bh[nt][0], bh[nt][1]);
#pragma unroll
            for (int nt = 0; nt < 4; nt++)
                mma16816h(acc[mt][nt], al, bh[nt][0], bh[nt][1]);
        }
        __syncthreads();
    }

    // ---- epilogue ----
    const float* bp = bias + (size_t)e * N_TOT + n0;
#pragma unroll
    for (int mt = 0; mt < 4; mt++) {
#pragma unroll
        for (int hlf = 0; hlf < 2; hlf++) {
            int m = m0 + wm + mt * 16 + gid + hlf * 8;
            if (m >= cnt) continue;
#pragma unroll
            for (int nt = 0; nt < 4; nt++) {
                int col = wn + nt * 8 + tg * 2;
                float v0 = acc[mt][nt][hlf * 2 + 0] + bp[col];
                float v1 = acc[mt][nt][hlf * 2 + 1] + bp[col + 1];
                if (G1) {
                    float2 g;
                    g.x = gelu_tanh(v0);
                    g.y = gelu_tanh(v1);
                    *(float2*)(d_hbuf + (size_t)(off + m) * F_DIM + n0 + col) = g;
                } else {
                    float2 v; v.x = v0; v.y = v1;
                    *(float2*)(d_ybuf + (size_t)(off + m) * H_DIM + n0 + col) = v;
                }
            }
        }
    }
}

__global__ void combine_kernel(float* __restrict__ out) {
    int idx = blockIdx.x * blockDim.x + threadIdx.x;
    if (idx >= T_TOK * (H_DIM / 4)) return;
    int t  = idx >> 8;
    int n4 = idx & 255;
    int   s0 = d_slot[2 * t + 0], s1 = d_slot[2 * t + 1];
    float w0 = d_wt[2 * t + 0],  w1 = d_wt[2 * t + 1];
    float4 a = *(const float4*)(d_ybuf + (size_t)s0 * H_DIM + n4 * 4);
    float4 b = *(const float4*)(d_ybuf + (size_t)s1 * H_DIM + n4 * 4);
    float4 o;
    o.x = w0 * a.x + w1 * b.x;
    o.y = w0 * a.y + w1 * b.y;
    o.z = w0 * a.z + w1 * b.z;
    o.w = w0 * a.w + w1 * b.w;
    *(float4*)(out + (size_t)t * H_DIM + n4 * 4) = o;
}

// ---------------- launch -----------------------------------------------------
extern "C" void kernel_launch(void* const* d_in, const int* in_sizes, int n_in,
                              void* d_out, int out_size) {
    const float* x  = (const float*)d_in[0];
    const float* rw = (const float*)d_in[1];
    const float* rb = (const float*)d_in[2];
    const float* w1 = (const float*)d_in[3];
    const float* b1 = (const float*)d_in[4];
    const float* w2 = (const float*)d_in[5];
    const float* b2 = (const float*)d_in[6];
    float* out = (float*)d_out;

    init_kernel<<<1, 32>>>();
    router_kernel<<<T_TOK / 4, 128>>>(x, rw, rb);
    offsets_kernel<<<1, 32>>>();
    scatter_kernel<<<(T_TOK + 255) / 256, 256>>>();

    dim3 g1(F_DIM / 128, T_TOK / 256, E_NUM);   // (32, 32, 8)
    moe_gemm<true><<<g1, 512>>>(x, w1, b1);
    dim3 g2(H_DIM / 128, T_TOK / 256, E_NUM);   // (8, 32, 8)
    moe_gemm<false><<<g2, 512>>>(x, w2, b2);

    combine_kernel<<<(T_TOK * (H_DIM / 4) + 255) / 256, 256>>>(out);
}